// round 1
// baseline (speedup 1.0000x reference)
#include <cuda_runtime.h>
#include <cstdint>

// Problem constants
#define BLROWS 4096   // B*L = 2*2048
#define LSEQ   2048
#define DMODEL 1024
#define DINNER 2048
#define DSTATE 16
#define DTRANK 64
#define XZCOLS 4096   // 2*DINNER

// ---------------------------------------------------------------------------
// Scratch (device globals: no allocation allowed in kernel_launch)
// ---------------------------------------------------------------------------
__device__ float g_xz[(size_t)BLROWS * XZCOLS];    // 64 MB  [4096,4096]
__device__ float g_u [(size_t)BLROWS * DINNER];    // 32 MB  conv-acc then silu
__device__ float g_dbc[(size_t)BLROWS * 96];       // 1.5 MB [dt(64)|B(16)|C(16)]
__device__ float g_delta[(size_t)BLROWS * DINNER]; // 32 MB
__device__ float g_y [(size_t)BLROWS * DINNER];    // 32 MB  y, then gated in-place

// ---------------------------------------------------------------------------
// Generic 128x128x16 fp32 tiled GEMM.  C[M,N] = A[M,K] @ B[K,N] (+bias, epi)
// Requirements: M % 128 == 0, K % 16 == 0 (true for all uses). N guarded.
// ---------------------------------------------------------------------------
enum { EPI_NONE = 0, EPI_SOFTPLUS_CLIP = 1 };

template <int EPI>
__global__ __launch_bounds__(256) void gemm_kernel(
    const float* __restrict__ A, int lda,
    const float* __restrict__ B, int ldb,
    float* __restrict__ C, int ldc,
    int N, int K, const float* __restrict__ bias)
{
    const int BM = 128, BN = 128, BK = 16;
    __shared__ float As[BK][BM];
    __shared__ float Bs[BK][BN];

    const int m0 = blockIdx.y * BM;
    const int n0 = blockIdx.x * BN;
    const int tid = threadIdx.x;
    const int tx = tid & 15;        // 0..15 -> 8 cols
    const int ty = tid >> 4;        // 0..15 -> 8 rows

    float acc[8][8];
#pragma unroll
    for (int i = 0; i < 8; i++)
#pragma unroll
        for (int j = 0; j < 8; j++) acc[i][j] = 0.f;

    for (int k0 = 0; k0 < K; k0 += BK) {
        // A tile: 128 rows x 16 k  (512 float4, 2 per thread), store transposed
#pragma unroll
        for (int i = 0; i < 2; i++) {
            int idx = tid + i * 256;
            int row = idx >> 2;
            int cv  = (idx & 3) * 4;
            float4 a = *(const float4*)(A + (size_t)(m0 + row) * lda + k0 + cv);
            As[cv + 0][row] = a.x;
            As[cv + 1][row] = a.y;
            As[cv + 2][row] = a.z;
            As[cv + 3][row] = a.w;
        }
        // B tile: 16 rows x 128 cols (512 float4, 2 per thread)
#pragma unroll
        for (int i = 0; i < 2; i++) {
            int idx  = tid + i * 256;
            int rowB = idx >> 5;
            int cv   = (idx & 31) * 4;
            float4 b = make_float4(0.f, 0.f, 0.f, 0.f);
            if (n0 + cv < N)
                b = *(const float4*)(B + (size_t)(k0 + rowB) * ldb + n0 + cv);
            *(float4*)(&Bs[rowB][cv]) = b;
        }
        __syncthreads();

#pragma unroll
        for (int k = 0; k < BK; k++) {
            float a[8], b[8];
            *(float4*)(a)     = *(const float4*)(&As[k][ty * 8]);
            *(float4*)(a + 4) = *(const float4*)(&As[k][ty * 8 + 4]);
            *(float4*)(b)     = *(const float4*)(&Bs[k][tx * 8]);
            *(float4*)(b + 4) = *(const float4*)(&Bs[k][tx * 8 + 4]);
#pragma unroll
            for (int i = 0; i < 8; i++)
#pragma unroll
                for (int j = 0; j < 8; j++)
                    acc[i][j] = fmaf(a[i], b[j], acc[i][j]);
        }
        __syncthreads();
    }

    // Epilogue + store
#pragma unroll
    for (int i = 0; i < 8; i++) {
        int m = m0 + ty * 8 + i;
#pragma unroll
        for (int jv = 0; jv < 8; jv += 4) {
            int n = n0 + tx * 8 + jv;
            if (n >= N) continue;
            float v[4];
#pragma unroll
            for (int j = 0; j < 4; j++) v[j] = acc[i][jv + j];
            if (EPI == EPI_SOFTPLUS_CLIP) {
#pragma unroll
                for (int j = 0; j < 4; j++) {
                    float x = v[j] + bias[n + j];
                    // stable softplus: max(x,0) + log1p(exp(-|x|))
                    float sp = fmaxf(x, 0.f) + log1pf(__expf(-fabsf(x)));
                    v[j] = fminf(fmaxf(sp, 1e-3f), 0.1f);
                }
            }
            float4 o = make_float4(v[0], v[1], v[2], v[3]);
            *(float4*)(C + (size_t)m * ldc + n) = o;
        }
    }
}

// ---------------------------------------------------------------------------
// Grouped causal conv as shifted GEMM-accumulate into g_u.
// xc[t,o] += sum_k xs[t + (W-3), g*1024 + k] * conv_k[W, k, o]
// Launch 4x (W=0..3). FIRST adds conv_b, LAST applies silu -> u.
// M=4096 (t), N=2048 (o), K=1024.
// ---------------------------------------------------------------------------
template <int W, bool FIRST, bool LAST>
__global__ __launch_bounds__(256) void conv_gemm_kernel(
    const float* __restrict__ XZ,     // [4096, 4096], xs = cols [0,2048)
    const float* __restrict__ CKw,    // conv_k + W*1024*2048, [1024, 2048]
    const float* __restrict__ convb,  // [2048]
    float* __restrict__ U)            // [4096, 2048]
{
    const int BM = 128, BN = 128, BK = 16;
    __shared__ float As[BK][BM];
    __shared__ float Bs[BK][BN];

    const int m0 = blockIdx.y * BM;
    const int n0 = blockIdx.x * BN;
    const int gbase = (n0 >= 1024) ? 1024 : 0;   // group input-channel base
    const int SH = W - 3;                        // row shift (<=0)
    const int tid = threadIdx.x;
    const int tx = tid & 15;
    const int ty = tid >> 4;

    float acc[8][8];
#pragma unroll
    for (int i = 0; i < 8; i++)
#pragma unroll
        for (int j = 0; j < 8; j++) acc[i][j] = 0.f;

    for (int k0 = 0; k0 < 1024; k0 += BK) {
#pragma unroll
        for (int i = 0; i < 2; i++) {
            int idx = tid + i * 256;
            int row = idx >> 2;
            int cv  = (idx & 3) * 4;
            int t   = m0 + row;
            float4 a = make_float4(0.f, 0.f, 0.f, 0.f);
            if ((t & (LSEQ - 1)) >= (3 - W))   // stay inside batch (causal pad)
                a = *(const float4*)(XZ + (size_t)(t + SH) * XZCOLS + gbase + k0 + cv);
            As[cv + 0][row] = a.x;
            As[cv + 1][row] = a.y;
            As[cv + 2][row] = a.z;
            As[cv + 3][row] = a.w;
        }
#pragma unroll
        for (int i = 0; i < 2; i++) {
            int idx  = tid + i * 256;
            int rowB = idx >> 5;
            int cv   = (idx & 31) * 4;
            *(float4*)(&Bs[rowB][cv]) =
                *(const float4*)(CKw + (size_t)(k0 + rowB) * DINNER + n0 + cv);
        }
        __syncthreads();

#pragma unroll
        for (int k = 0; k < BK; k++) {
            float a[8], b[8];
            *(float4*)(a)     = *(const float4*)(&As[k][ty * 8]);
            *(float4*)(a + 4) = *(const float4*)(&As[k][ty * 8 + 4]);
            *(float4*)(b)     = *(const float4*)(&Bs[k][tx * 8]);
            *(float4*)(b + 4) = *(const float4*)(&Bs[k][tx * 8 + 4]);
#pragma unroll
            for (int i = 0; i < 8; i++)
#pragma unroll
                for (int j = 0; j < 8; j++)
                    acc[i][j] = fmaf(a[i], b[j], acc[i][j]);
        }
        __syncthreads();
    }

#pragma unroll
    for (int i = 0; i < 8; i++) {
        int m = m0 + ty * 8 + i;
#pragma unroll
        for (int jv = 0; jv < 8; jv += 4) {
            int n = n0 + tx * 8 + jv;
            float* up = U + (size_t)m * DINNER + n;
            float v[4];
#pragma unroll
            for (int j = 0; j < 4; j++) v[j] = acc[i][jv + j];
            if (FIRST) {
#pragma unroll
                for (int j = 0; j < 4; j++) v[j] += convb[n + j];
            } else {
                float4 old = *(const float4*)up;
                v[0] += old.x; v[1] += old.y; v[2] += old.z; v[3] += old.w;
            }
            if (LAST) {
#pragma unroll
                for (int j = 0; j < 4; j++)
                    v[j] = v[j] / (1.f + __expf(-v[j]));   // silu
            }
            *(float4*)up = make_float4(v[0], v[1], v[2], v[3]);
        }
    }
}

// ---------------------------------------------------------------------------
// Narrow GEMM: DBC[4096,96] = U[4096,2048] @ W_x[2048,96]
// BM=32 so grid=128 blocks (parallelism for tiny-N case).
// ---------------------------------------------------------------------------
__global__ __launch_bounds__(256) void gemm_n96_kernel(
    const float* __restrict__ A,   // U [4096, 2048]
    const float* __restrict__ B,   // W_x [2048, 96]
    float* __restrict__ C)         // [4096, 96]
{
    const int BM = 32, BK = 32, NN = 96;
    __shared__ float As[BK][BM];
    __shared__ float Bs[BK][NN];

    const int m0 = blockIdx.x * BM;
    const int tid = threadIdx.x;
    const int tx = tid & 15;   // 6 cols each
    const int ty = tid >> 4;   // 2 rows each

    float acc[2][6];
#pragma unroll
    for (int r = 0; r < 2; r++)
#pragma unroll
        for (int j = 0; j < 6; j++) acc[r][j] = 0.f;

    for (int k0 = 0; k0 < DINNER; k0 += BK) {
        {   // A tile 32x32 -> 256 float4, 1 per thread, transposed
            int row = tid >> 3;
            int cv  = (tid & 7) * 4;
            float4 a = *(const float4*)(A + (size_t)(m0 + row) * DINNER + k0 + cv);
            As[cv + 0][row] = a.x;
            As[cv + 1][row] = a.y;
            As[cv + 2][row] = a.z;
            As[cv + 3][row] = a.w;
        }
#pragma unroll
        for (int i = 0; i < 3; i++) {   // B tile 32x96 -> 768 float4, 3/thread
            int idx  = tid + i * 256;
            int rowB = idx / 24;
            int cv   = (idx % 24) * 4;
            *(float4*)(&Bs[rowB][cv]) =
                *(const float4*)(B + (size_t)(k0 + rowB) * NN + cv);
        }
        __syncthreads();

#pragma unroll
        for (int k = 0; k < BK; k++) {
            float a0 = As[k][ty * 2];
            float a1 = As[k][ty * 2 + 1];
#pragma unroll
            for (int j = 0; j < 6; j++) {
                float bb = Bs[k][tx * 6 + j];
                acc[0][j] = fmaf(a0, bb, acc[0][j]);
                acc[1][j] = fmaf(a1, bb, acc[1][j]);
            }
        }
        __syncthreads();
    }

#pragma unroll
    for (int r = 0; r < 2; r++) {
        int m = m0 + ty * 2 + r;
#pragma unroll
        for (int j = 0; j < 6; j++)
            C[(size_t)m * NN + tx * 6 + j] = acc[r][j];
    }
}

// ---------------------------------------------------------------------------
// Selective scan: thread = (b, d, n). 65536 threads, sequential over t.
// h = exp(delta*A)*h + delta*u*B ;  y = sum_n h*C + u*D
// ---------------------------------------------------------------------------
__global__ __launch_bounds__(256) void scan_kernel(
    const float* __restrict__ delta,  // [B*L, 2048]
    const float* __restrict__ u,      // [B*L, 2048]
    const float* __restrict__ dbc,    // [B*L, 96]
    const float* __restrict__ A_log,  // [2048, 16]
    const float* __restrict__ Dp,     // [2048]
    float* __restrict__ Y)            // [B*L, 2048]
{
    int tid = blockIdx.x * blockDim.x + threadIdx.x;   // 0..65535
    int n = tid & 15;
    int d = (tid >> 4) & (DINNER - 1);
    int b = tid >> 15;

    const float a  = -__expf(A_log[d * DSTATE + n]);
    const float Dd = Dp[d];

    const size_t rowbase = (size_t)b * LSEQ;
    const float* dptr = delta + rowbase * DINNER + d;
    const float* uptr = u     + rowbase * DINNER + d;
    const float* bc   = dbc   + rowbase * 96;
    float*       yp   = Y     + rowbase * DINNER + d;

    float h = 0.f;
    for (int t = 0; t < LSEQ; t++) {
        float de = dptr[(size_t)t * DINNER];
        float uu = uptr[(size_t)t * DINNER];
        float Bn = bc[t * 96 + DTRANK + n];
        float Cn = bc[t * 96 + DTRANK + DSTATE + n];
        float dA = __expf(de * a);
        h = fmaf(dA, h, de * uu * Bn);
        float p = h * Cn;
        p += __shfl_xor_sync(0xffffffffu, p, 8);
        p += __shfl_xor_sync(0xffffffffu, p, 4);
        p += __shfl_xor_sync(0xffffffffu, p, 2);
        p += __shfl_xor_sync(0xffffffffu, p, 1);
        if (n == 0) yp[(size_t)t * DINNER] = fmaf(uu, Dd, p);
    }
}

// ---------------------------------------------------------------------------
// Gate: Y *= silu(res), res = XZ[:, 2048:]
// ---------------------------------------------------------------------------
__global__ __launch_bounds__(256) void gate_kernel(
    float* __restrict__ Y, const float* __restrict__ XZ)
{
    size_t i = (size_t)blockIdx.x * blockDim.x + threadIdx.x;  // float4 index
    size_t row = i >> 9;          // 512 float4 per row
    size_t c4  = i & 511;
    float4 y = ((float4*)Y)[i];
    float4 r = *(const float4*)(XZ + row * XZCOLS + DINNER + c4 * 4);
    y.x *= r.x / (1.f + __expf(-r.x));
    y.y *= r.y / (1.f + __expf(-r.y));
    y.z *= r.z / (1.f + __expf(-r.z));
    y.w *= r.w / (1.f + __expf(-r.w));
    ((float4*)Y)[i] = y;
}

// ---------------------------------------------------------------------------
// Launch
// ---------------------------------------------------------------------------
extern "C" void kernel_launch(void* const* d_in, const int* in_sizes, int n_in,
                              void* d_out, int out_size)
{
    (void)in_sizes; (void)n_in; (void)out_size;
    const float* x      = (const float*)d_in[0];   // [2,2048,1024]
    const float* W_in   = (const float*)d_in[1];   // [1024,4096]
    const float* conv_k = (const float*)d_in[2];   // [4,1024,2048]
    const float* conv_b = (const float*)d_in[3];   // [2048]
    const float* W_x    = (const float*)d_in[4];   // [2048,96]
    const float* W_dt   = (const float*)d_in[5];   // [64,2048]
    const float* b_dt   = (const float*)d_in[6];   // [2048]
    const float* A_log  = (const float*)d_in[7];   // [2048,16]
    const float* Dvec   = (const float*)d_in[8];   // [2048]
    const float* W_out  = (const float*)d_in[9];   // [2048,1024]
    float* out = (float*)d_out;                    // [2,2048,1024]

    float *xz, *u, *dbc, *delta, *y;
    cudaGetSymbolAddress((void**)&xz,    g_xz);
    cudaGetSymbolAddress((void**)&u,     g_u);
    cudaGetSymbolAddress((void**)&dbc,   g_dbc);
    cudaGetSymbolAddress((void**)&delta, g_delta);
    cudaGetSymbolAddress((void**)&y,     g_y);

    // 1) xz = x @ W_in   [4096,4096]
    gemm_kernel<EPI_NONE><<<dim3(32, 32), 256>>>(
        x, DMODEL, W_in, XZCOLS, xz, XZCOLS, XZCOLS, DMODEL, nullptr);

    // 2) grouped causal conv (4 taps) + bias, silu fused on last tap -> u
    const size_t ckstride = (size_t)1024 * DINNER;
    conv_gemm_kernel<0, true,  false><<<dim3(16, 32), 256>>>(xz, conv_k + 0 * ckstride, conv_b, u);
    conv_gemm_kernel<1, false, false><<<dim3(16, 32), 256>>>(xz, conv_k + 1 * ckstride, conv_b, u);
    conv_gemm_kernel<2, false, false><<<dim3(16, 32), 256>>>(xz, conv_k + 2 * ckstride, conv_b, u);
    conv_gemm_kernel<3, false, true ><<<dim3(16, 32), 256>>>(xz, conv_k + 3 * ckstride, conv_b, u);

    // 3) dbc = u @ W_x   [4096,96]
    gemm_n96_kernel<<<128, 256>>>(u, W_x, dbc);

    // 4) delta = clip(softplus(dbc[:,:64] @ W_dt + b_dt))  [4096,2048]
    gemm_kernel<EPI_SOFTPLUS_CLIP><<<dim3(16, 32), 256>>>(
        dbc, 96, W_dt, DINNER, delta, DINNER, DINNER, DTRANK, b_dt);

    // 5) selective scan -> y (includes + u*D)
    scan_kernel<<<256, 256>>>(delta, u, dbc, A_log, Dvec, y);

    // 6) y *= silu(res)
    gate_kernel<<<(BLROWS * DINNER / 4) / 256, 256>>>(y, xz);

    // 7) out = y @ W_out  [4096,1024]
    gemm_kernel<EPI_NONE><<<dim3(8, 32), 256>>>(
        y, DINNER, W_out, DMODEL, out, DMODEL, DMODEL, DINNER, nullptr);
}

// round 3
// speedup vs baseline: 1.7074x; 1.7074x over previous
#include <cuda_runtime.h>
#include <cuda_bf16.h>
#include <cstdint>

// Problem constants
#define BLROWS 4096   // B*L = 2*2048
#define LSEQ   2048
#define DMODEL 1024
#define DINNER 2048
#define DSTATE 16
#define DTRANK 64
#define XZCOLS 4096   // 2*DINNER

// ---------------------------------------------------------------------------
// Scratch (device globals)
// ---------------------------------------------------------------------------
__device__ float g_xz[(size_t)BLROWS * XZCOLS];    // 64 MB
__device__ float g_u [(size_t)BLROWS * DINNER];    // 32 MB
__device__ float g_dbc[(size_t)BLROWS * 96];       // 1.5 MB
__device__ float g_delta[(size_t)BLROWS * DINNER]; // 32 MB
__device__ float g_y [(size_t)BLROWS * DINNER];    // 32 MB
// Transposed weights ([N,K] K-major)
__device__ float g_WinT [(size_t)4096 * 1024];     // 16 MB
__device__ float g_convT[(size_t)4 * 2048 * 1024]; // 32 MB
__device__ float g_WoutT[(size_t)1024 * 2048];     // 8 MB
__device__ float g_WdtT [(size_t)2048 * 64];       // 0.5 MB

// ---------------------------------------------------------------------------
// mma.sync / ldmatrix helpers (baseline PTX, legal on compute_103)
// ---------------------------------------------------------------------------
__device__ __forceinline__ uint32_t smem_u32(const void* p) {
    uint32_t a;
    asm("{ .reg .u64 t; cvta.to.shared.u64 t, %1; cvt.u32.u64 %0, t; }"
        : "=r"(a) : "l"(p));
    return a;
}
__device__ __forceinline__ void ldsm4(uint32_t* r, uint32_t addr) {
    asm volatile("ldmatrix.sync.aligned.m8n8.x4.shared.b16 {%0,%1,%2,%3}, [%4];"
        : "=r"(r[0]), "=r"(r[1]), "=r"(r[2]), "=r"(r[3]) : "r"(addr));
}
__device__ __forceinline__ void mma16816(
    float& d0, float& d1, float& d2, float& d3,
    uint32_t a0, uint32_t a1, uint32_t a2, uint32_t a3,
    uint32_t b0, uint32_t b1)
{
    asm volatile(
        "mma.sync.aligned.m16n8k16.row.col.f32.bf16.bf16.f32 "
        "{%0,%1,%2,%3}, {%4,%5,%6,%7}, {%8,%9}, {%0,%1,%2,%3};"
        : "+f"(d0), "+f"(d1), "+f"(d2), "+f"(d3)
        : "r"(a0), "r"(a1), "r"(a2), "r"(a3), "r"(b0), "r"(b1));
}
// bf16 2-way split of a pair of floats -> packed bf16x2 (hi, lo)
__device__ __forceinline__ void split2(float x, float y, uint32_t& hi, uint32_t& lo) {
    __nv_bfloat16 hx = __float2bfloat16_rn(x);
    __nv_bfloat16 hy = __float2bfloat16_rn(y);
    __nv_bfloat162 h; h.x = hx; h.y = hy;
    __nv_bfloat162 l = __floats2bfloat162_rn(x - __bfloat162float(hx),
                                             y - __bfloat162float(hy));
    hi = *reinterpret_cast<uint32_t*>(&h);
    lo = *reinterpret_cast<uint32_t*>(&l);
}
// SMEM tile layout: 128 rows x 32 bf16 (4 chunks of 16B), xor-swizzled
__device__ __forceinline__ uint32_t swz(int row, int chunk) {
    return (uint32_t)((row << 6) + (((chunk ^ ((row >> 1) & 3)) & 3) << 4));
}

// ---------------------------------------------------------------------------
// bf16x3 mma GEMM.  C[128,128]-tile = A[M,K] @ Bt[N,K]^T  (fp32 in/out)
// NTAPS=1: plain GEMM. NTAPS=4: grouped causal conv (row shift per tap,
// group column base from n-tile), accumulated in registers across taps.
// EPI: 0 none, 1 softplus+clip(+bias), 2 bias+silu.
// ---------------------------------------------------------------------------
template <int NTAPS, int EPI>
__global__ __launch_bounds__(256) void mma_gemm(
    const float* __restrict__ A, int lda,
    const float* __restrict__ Bt, long tap_stride, int ldb,
    float* __restrict__ C, int ldc,
    int K, const float* __restrict__ bias)
{
    __shared__ __align__(16) char sAhi[8192], sAlo[8192], sBhi[8192], sBlo[8192];

    const int tid  = threadIdx.x;
    const int lane = tid & 31;
    const int wid  = tid >> 5;
    const int wm   = wid & 1;        // warp row (2)
    const int wn   = wid >> 1;       // warp col (4)
    const int m0   = blockIdx.y * 128;
    const int n0   = blockIdx.x * 128;
    const int colbase = (NTAPS == 4 && n0 >= 1024) ? 1024 : 0;
    const int NKB = K >> 5;
    const int TOT = NTAPS * NKB;

    const uint32_t aHiB = smem_u32(sAhi), aLoB = smem_u32(sAlo);
    const uint32_t bHiB = smem_u32(sBhi), bLoB = smem_u32(sBlo);

    // per-lane ldmatrix source coordinates
    const int a_r  = lane & 15;           // row within 16-row frag
    const int a_cx = lane >> 4;           // chunk offset 0/1
    const int b_r  = (lane & 7) + ((lane >> 4) << 3);
    const int b_cx = (lane >> 3) & 1;

    float acc[4][4][4];
#pragma unroll
    for (int i = 0; i < 4; i++)
#pragma unroll
        for (int j = 0; j < 4; j++)
#pragma unroll
            for (int k = 0; k < 4; k++) acc[i][j][k] = 0.f;

    float4 pa[4], pb[4];

    auto load = [&](int it) {
        int tap = (NTAPS == 1) ? 0 : (it / NKB);
        int kb  = it - tap * NKB;
        const float* Bw = Bt + (long)tap * tap_stride;
#pragma unroll
        for (int i = 0; i < 4; i++) {
            int idx = tid + i * 256;
            int row = idx >> 3, seg = idx & 7;
            float4 av;
            if (NTAPS == 4) {
                int t = m0 + row;
                if ((t & (LSEQ - 1)) >= (3 - tap))
                    av = *(const float4*)(A + (size_t)(t + tap - 3) * lda + colbase + kb * 32 + seg * 4);
                else
                    av = make_float4(0.f, 0.f, 0.f, 0.f);
            } else {
                av = *(const float4*)(A + (size_t)(m0 + row) * lda + kb * 32 + seg * 4);
            }
            pa[i] = av;
            pb[i] = *(const float4*)(Bw + (size_t)(n0 + row) * ldb + kb * 32 + seg * 4);
        }
    };

    auto store = [&]() {
#pragma unroll
        for (int i = 0; i < 4; i++) {
            int idx = tid + i * 256;
            int row = idx >> 3, seg = idx & 7;
            uint32_t off = swz(row, seg >> 1) + (seg & 1) * 8;
            uint2 h, l;
            split2(pa[i].x, pa[i].y, h.x, l.x);
            split2(pa[i].z, pa[i].w, h.y, l.y);
            *(uint2*)(sAhi + off) = h;
            *(uint2*)(sAlo + off) = l;
            split2(pb[i].x, pb[i].y, h.x, l.x);
            split2(pb[i].z, pb[i].w, h.y, l.y);
            *(uint2*)(sBhi + off) = h;
            *(uint2*)(sBlo + off) = l;
        }
    };

    auto mma_block = [&]() {
#pragma unroll
        for (int ks = 0; ks < 2; ks++) {
            uint32_t a[4][4], bh[4][2], bx[4][2];
            // A-hi frags
#pragma unroll
            for (int mf = 0; mf < 4; mf++) {
                int row = wm * 64 + mf * 16 + a_r;
                ldsm4(a[mf], aHiB + swz(row, ks * 2 + a_cx));
            }
            // B-hi frags (two x4 loads cover 4 n-frags)
#pragma unroll
            for (int p = 0; p < 2; p++) {
                int row = wn * 32 + p * 16 + b_r;
                uint32_t t[4];
                ldsm4(t, bHiB + swz(row, ks * 2 + b_cx));
                bh[p * 2][0] = t[0]; bh[p * 2][1] = t[1];
                bh[p * 2 + 1][0] = t[2]; bh[p * 2 + 1][1] = t[3];
            }
#pragma unroll
            for (int mf = 0; mf < 4; mf++)
#pragma unroll
                for (int nf = 0; nf < 4; nf++)
                    mma16816(acc[mf][nf][0], acc[mf][nf][1], acc[mf][nf][2], acc[mf][nf][3],
                             a[mf][0], a[mf][1], a[mf][2], a[mf][3], bh[nf][0], bh[nf][1]);
            // B-lo frags  (hi*lo)
#pragma unroll
            for (int p = 0; p < 2; p++) {
                int row = wn * 32 + p * 16 + b_r;
                uint32_t t[4];
                ldsm4(t, bLoB + swz(row, ks * 2 + b_cx));
                bx[p * 2][0] = t[0]; bx[p * 2][1] = t[1];
                bx[p * 2 + 1][0] = t[2]; bx[p * 2 + 1][1] = t[3];
            }
#pragma unroll
            for (int mf = 0; mf < 4; mf++)
#pragma unroll
                for (int nf = 0; nf < 4; nf++)
                    mma16816(acc[mf][nf][0], acc[mf][nf][1], acc[mf][nf][2], acc[mf][nf][3],
                             a[mf][0], a[mf][1], a[mf][2], a[mf][3], bx[nf][0], bx[nf][1]);
            // A-lo frags  (lo*hi)
#pragma unroll
            for (int mf = 0; mf < 4; mf++) {
                int row = wm * 64 + mf * 16 + a_r;
                ldsm4(a[mf], aLoB + swz(row, ks * 2 + a_cx));
            }
#pragma unroll
            for (int mf = 0; mf < 4; mf++)
#pragma unroll
                for (int nf = 0; nf < 4; nf++)
                    mma16816(acc[mf][nf][0], acc[mf][nf][1], acc[mf][nf][2], acc[mf][nf][3],
                             a[mf][0], a[mf][1], a[mf][2], a[mf][3], bh[nf][0], bh[nf][1]);
        }
    };

    load(0);
    store();
    __syncthreads();
    for (int it = 1; it < TOT; it++) {
        load(it);        // prefetch next tile into registers
        mma_block();     // compute on current SMEM tile
        __syncthreads();
        store();
        __syncthreads();
    }
    mma_block();

    // Epilogue
#pragma unroll
    for (int mf = 0; mf < 4; mf++) {
        int r = m0 + wm * 64 + mf * 16 + (lane >> 2);
#pragma unroll
        for (int nf = 0; nf < 4; nf++) {
            int c = n0 + wn * 32 + nf * 8 + (lane & 3) * 2;
            float v0 = acc[mf][nf][0], v1 = acc[mf][nf][1];
            float v2 = acc[mf][nf][2], v3 = acc[mf][nf][3];
            if (EPI == 1) {   // softplus + clip (delta)
                float b0 = bias[c], b1 = bias[c + 1];
                float x0 = v0 + b0, x1 = v1 + b1, x2 = v2 + b0, x3 = v3 + b1;
                v0 = fminf(fmaxf(fmaxf(x0, 0.f) + log1pf(__expf(-fabsf(x0))), 1e-3f), 0.1f);
                v1 = fminf(fmaxf(fmaxf(x1, 0.f) + log1pf(__expf(-fabsf(x1))), 1e-3f), 0.1f);
                v2 = fminf(fmaxf(fmaxf(x2, 0.f) + log1pf(__expf(-fabsf(x2))), 1e-3f), 0.1f);
                v3 = fminf(fmaxf(fmaxf(x3, 0.f) + log1pf(__expf(-fabsf(x3))), 1e-3f), 0.1f);
            } else if (EPI == 2) {   // bias + silu (conv)
                float b0 = bias[c], b1 = bias[c + 1];
                v0 += b0; v1 += b1; v2 += b0; v3 += b1;
                v0 = v0 / (1.f + __expf(-v0));
                v1 = v1 / (1.f + __expf(-v1));
                v2 = v2 / (1.f + __expf(-v2));
                v3 = v3 / (1.f + __expf(-v3));
            }
            *(float2*)(C + (size_t)r * ldc + c)       = make_float2(v0, v1);
            *(float2*)(C + (size_t)(r + 8) * ldc + c) = make_float2(v2, v3);
        }
    }
}

// ---------------------------------------------------------------------------
// Transpose [R,C] -> [C,R].  R,C multiples of 32.
// ---------------------------------------------------------------------------
__global__ __launch_bounds__(256) void transpose_kernel(
    const float* __restrict__ src, float* __restrict__ dst, int R, int C)
{
    __shared__ float t[32][33];
    int x = blockIdx.x * 32 + threadIdx.x;
#pragma unroll
    for (int j = 0; j < 4; j++) {
        int y = blockIdx.y * 32 + threadIdx.y + j * 8;
        t[threadIdx.y + j * 8][threadIdx.x] = src[(size_t)y * C + x];
    }
    __syncthreads();
    int x2 = blockIdx.y * 32 + threadIdx.x;
#pragma unroll
    for (int j = 0; j < 4; j++) {
        int y2 = blockIdx.x * 32 + threadIdx.y + j * 8;
        dst[(size_t)y2 * R + x2] = t[threadIdx.x][threadIdx.y + j * 8];
    }
}

// ---------------------------------------------------------------------------
// Narrow GEMM: DBC[4096,96] = U @ W_x (fp32 SIMT; exact inputs for scan B/C)
// ---------------------------------------------------------------------------
__global__ __launch_bounds__(256) void gemm_n96_kernel(
    const float* __restrict__ A, const float* __restrict__ B, float* __restrict__ C)
{
    const int BM = 32, BK = 32, NN = 96;
    __shared__ float As[BK][BM];
    __shared__ float Bs[BK][NN];

    const int m0 = blockIdx.x * BM;
    const int tid = threadIdx.x;
    const int tx = tid & 15;
    const int ty = tid >> 4;

    float acc[2][6];
#pragma unroll
    for (int r = 0; r < 2; r++)
#pragma unroll
        for (int j = 0; j < 6; j++) acc[r][j] = 0.f;

    for (int k0 = 0; k0 < DINNER; k0 += BK) {
        {
            int row = tid >> 3;
            int cv  = (tid & 7) * 4;
            float4 a = *(const float4*)(A + (size_t)(m0 + row) * DINNER + k0 + cv);
            As[cv + 0][row] = a.x; As[cv + 1][row] = a.y;
            As[cv + 2][row] = a.z; As[cv + 3][row] = a.w;
        }
#pragma unroll
        for (int i = 0; i < 3; i++) {
            int idx  = tid + i * 256;
            int rowB = idx / 24;
            int cv   = (idx % 24) * 4;
            *(float4*)(&Bs[rowB][cv]) =
                *(const float4*)(B + (size_t)(k0 + rowB) * NN + cv);
        }
        __syncthreads();
#pragma unroll
        for (int k = 0; k < BK; k++) {
            float a0 = As[k][ty * 2];
            float a1 = As[k][ty * 2 + 1];
#pragma unroll
            for (int j = 0; j < 6; j++) {
                float bb = Bs[k][tx * 6 + j];
                acc[0][j] = fmaf(a0, bb, acc[0][j]);
                acc[1][j] = fmaf(a1, bb, acc[1][j]);
            }
        }
        __syncthreads();
    }
#pragma unroll
    for (int r = 0; r < 2; r++) {
        int m = m0 + ty * 2 + r;
#pragma unroll
        for (int j = 0; j < 6; j++)
            C[(size_t)m * 96 + tx * 6 + j] = acc[r][j];
    }
}

// ---------------------------------------------------------------------------
// Selective scan
// ---------------------------------------------------------------------------
__global__ __launch_bounds__(256) void scan_kernel(
    const float* __restrict__ delta, const float* __restrict__ u,
    const float* __restrict__ dbc, const float* __restrict__ A_log,
    const float* __restrict__ Dp, float* __restrict__ Y)
{
    int tid = blockIdx.x * blockDim.x + threadIdx.x;
    int n = tid & 15;
    int d = (tid >> 4) & (DINNER - 1);
    int b = tid >> 15;

    const float a  = -__expf(A_log[d * DSTATE + n]);
    const float Dd = Dp[d];

    const size_t rowbase = (size_t)b * LSEQ;
    const float* dptr = delta + rowbase * DINNER + d;
    const float* uptr = u     + rowbase * DINNER + d;
    const float* bc   = dbc   + rowbase * 96;
    float*       yp   = Y     + rowbase * DINNER + d;

    float h = 0.f;
    for (int t = 0; t < LSEQ; t++) {
        float de = dptr[(size_t)t * DINNER];
        float uu = uptr[(size_t)t * DINNER];
        float Bn = bc[t * 96 + DTRANK + n];
        float Cn = bc[t * 96 + DTRANK + DSTATE + n];
        float dA = __expf(de * a);
        h = fmaf(dA, h, de * uu * Bn);
        float p = h * Cn;
        p += __shfl_xor_sync(0xffffffffu, p, 8);
        p += __shfl_xor_sync(0xffffffffu, p, 4);
        p += __shfl_xor_sync(0xffffffffu, p, 2);
        p += __shfl_xor_sync(0xffffffffu, p, 1);
        if (n == 0) yp[(size_t)t * DINNER] = fmaf(uu, Dd, p);
    }
}

// ---------------------------------------------------------------------------
// Gate: Y *= silu(res)
// ---------------------------------------------------------------------------
__global__ __launch_bounds__(256) void gate_kernel(
    float* __restrict__ Y, const float* __restrict__ XZ)
{
    size_t i = (size_t)blockIdx.x * blockDim.x + threadIdx.x;
    size_t row = i >> 9;
    size_t c4  = i & 511;
    float4 y = ((float4*)Y)[i];
    float4 r = *(const float4*)(XZ + row * XZCOLS + DINNER + c4 * 4);
    y.x *= r.x / (1.f + __expf(-r.x));
    y.y *= r.y / (1.f + __expf(-r.y));
    y.z *= r.z / (1.f + __expf(-r.z));
    y.w *= r.w / (1.f + __expf(-r.w));
    ((float4*)Y)[i] = y;
}

// ---------------------------------------------------------------------------
// Launch
// ---------------------------------------------------------------------------
extern "C" void kernel_launch(void* const* d_in, const int* in_sizes, int n_in,
                              void* d_out, int out_size)
{
    (void)in_sizes; (void)n_in; (void)out_size;
    const float* x      = (const float*)d_in[0];
    const float* W_in   = (const float*)d_in[1];
    const float* conv_k = (const float*)d_in[2];
    const float* conv_b = (const float*)d_in[3];
    const float* W_x    = (const float*)d_in[4];
    const float* W_dt   = (const float*)d_in[5];
    const float* b_dt   = (const float*)d_in[6];
    const float* A_log  = (const float*)d_in[7];
    const float* Dvec   = (const float*)d_in[8];
    const float* W_out  = (const float*)d_in[9];
    float* out = (float*)d_out;

    float *xz, *u, *dbc, *delta, *y, *winT, *convT, *woutT, *wdtT;
    cudaGetSymbolAddress((void**)&xz,    g_xz);
    cudaGetSymbolAddress((void**)&u,     g_u);
    cudaGetSymbolAddress((void**)&dbc,   g_dbc);
    cudaGetSymbolAddress((void**)&delta, g_delta);
    cudaGetSymbolAddress((void**)&y,     g_y);
    cudaGetSymbolAddress((void**)&winT,  g_WinT);
    cudaGetSymbolAddress((void**)&convT, g_convT);
    cudaGetSymbolAddress((void**)&woutT, g_WoutT);
    cudaGetSymbolAddress((void**)&wdtT,  g_WdtT);

    // 0) Transpose weights to [N,K]
    transpose_kernel<<<dim3(4096 / 32, 1024 / 32), dim3(32, 8)>>>(W_in, winT, 1024, 4096);
    for (int w = 0; w < 4; w++)
        transpose_kernel<<<dim3(2048 / 32, 1024 / 32), dim3(32, 8)>>>(
            conv_k + (size_t)w * 1024 * 2048, convT + (size_t)w * 2048 * 1024, 1024, 2048);
    transpose_kernel<<<dim3(1024 / 32, 2048 / 32), dim3(32, 8)>>>(W_out, woutT, 2048, 1024);
    transpose_kernel<<<dim3(2048 / 32, 64 / 32), dim3(32, 8)>>>(W_dt, wdtT, 64, 2048);

    // 1) xz = x @ W_in  (bf16x3 mma)
    mma_gemm<1, 0><<<dim3(4096 / 128, 4096 / 128), 256>>>(
        x, DMODEL, winT, 0, DMODEL, xz, XZCOLS, DMODEL, nullptr);

    // 2) grouped causal conv, 4 taps fused -> u (bias + silu)
    mma_gemm<4, 2><<<dim3(2048 / 128, 4096 / 128), 256>>>(
        xz, XZCOLS, convT, (long)2048 * 1024, 1024, u, DINNER, 1024, conv_b);

    // 3) dbc = u @ W_x  (fp32 SIMT, exact B/C for scan)
    gemm_n96_kernel<<<128, 256>>>(u, W_x, dbc);

    // 4) delta = clip(softplus(dt_raw @ W_dt + b_dt))  (bf16x3 mma, K=64)
    mma_gemm<1, 1><<<dim3(2048 / 128, 4096 / 128), 256>>>(
        dbc, 96, wdtT, 0, DTRANK, delta, DINNER, DTRANK, b_dt);

    // 5) selective scan -> y
    scan_kernel<<<256, 256>>>(delta, u, dbc, A_log, Dvec, y);

    // 6) gate
    gate_kernel<<<(BLROWS * DINNER / 4) / 256, 256>>>(y, xz);

    // 7) out = y @ W_out  (bf16x3 mma)
    mma_gemm<1, 0><<<dim3(1024 / 128, 4096 / 128), 256>>>(
        y, DINNER, woutT, 0, DINNER, out, DMODEL, DINNER, nullptr);
}